// round 16
// baseline (speedup 1.0000x reference)
#include <cuda_runtime.h>
#include <cuda_bf16.h>
#include <cuda_fp16.h>
#include <cstdint>

#define BSZ  512
#define TLEN 512
#define IDIM 128
#define HDIM 50
#define ODIM 10
#define GDIM 200              // 4*H
#define BT   (BSZ * TLEN)     // 262144 rows
#define NTILES 2048           // BT / 128
#define PGRID  296            // 148 SMs x 2 blocks

typedef unsigned long long u64;
typedef unsigned int u32;

// ---- scratch (device globals; no allocation allowed) ----
__device__ u32   g_Bimg[102400 / 4];        // W_ih bf16 hi/lo frag image (prescaled i/f/o)
__device__ float g_Whs[GDIM * HDIM];        // W_hh prescaled copy
__device__ float g_bias[GDIM];              // (b_ih + b_hh) prescaled
__device__ unsigned short g_xph[(size_t)BT * GDIM];   // x_proj in fp16

// ---- packed f32x2 helpers ----
__device__ __forceinline__ u64 pk2(float lo, float hi) {
    u64 d;
    asm("mov.b64 %0, {%1, %2};" : "=l"(d) : "f"(lo), "f"(hi));
    return d;
}
__device__ __forceinline__ void up2(u64 v, float& lo, float& hi) {
    asm("mov.b64 {%0, %1}, %2;" : "=f"(lo), "=f"(hi) : "l"(v));
}
__device__ __forceinline__ u64 ffma2(u64 a, u64 b, u64 c) {
    u64 d;
    asm("fma.rn.f32x2 %0, %1, %2, %3;" : "=l"(d) : "l"(a), "l"(b), "l"(c));
    return d;
}
__device__ __forceinline__ u64 fadd2(u64 a, u64 b) {
    u64 d;
    asm("add.rn.f32x2 %0, %1, %2;" : "=l"(d) : "l"(a), "l"(b));
    return d;
}
__device__ __forceinline__ float tanha(float x) {
    float r;
    asm("tanh.approx.f32 %0, %1;" : "=f"(r) : "f"(x));
    return r;
}
__device__ __forceinline__ void cp16(void* smem, const void* gmem) {
    unsigned sa = (unsigned)__cvta_generic_to_shared(smem);
    asm volatile("cp.async.cg.shared.global [%0], [%1], 16;\n" :: "r"(sa), "l"(gmem));
}
// slow exact split (prep only)
__device__ __forceinline__ void split_bf16(float v, unsigned short& h, unsigned short& l) {
    __nv_bfloat16 hb = __float2bfloat16_rn(v);
    float lf = v - __bfloat162float(hb);
    __nv_bfloat16 lb = __float2bfloat16_rn(lf);
    h = __bfloat16_as_ushort(hb);
    l = __bfloat16_as_ushort(lb);
}
__device__ __forceinline__ void split2(float2 v, u32& hp, u32& lp) {
    unsigned short h0, l0, h1, l1;
    split_bf16(v.x, h0, l0);
    split_bf16(v.y, h1, l1);
    hp = (u32)h0 | ((u32)h1 << 16);
    lp = (u32)l0 | ((u32)l1 << 16);
}
// fast split: 1 packed cvt for hi, shift/mask reconstruct, 2 subs, 1 packed cvt for lo
__device__ __forceinline__ void split2f(float2 v, u32& hp, u32& lp) {
    asm("cvt.rn.satfinite.bf16x2.f32 %0, %1, %2;" : "=r"(hp) : "f"(v.y), "f"(v.x));
    float h0 = __uint_as_float(hp << 16);
    float h1 = __uint_as_float(hp & 0xffff0000u);
    float l0 = v.x - h0;
    float l1 = v.y - h1;
    asm("cvt.rn.satfinite.bf16x2.f32 %0, %1, %2;" : "=r"(lp) : "f"(l1), "f"(l0));
}
__device__ __forceinline__ void mma16816(float* c, const u32* a, u32 b0, u32 b1) {
    asm volatile(
        "mma.sync.aligned.m16n8k16.row.col.f32.bf16.bf16.f32 "
        "{%0,%1,%2,%3}, {%4,%5,%6,%7}, {%8,%9}, {%0,%1,%2,%3};"
        : "+f"(c[0]), "+f"(c[1]), "+f"(c[2]), "+f"(c[3])
        : "r"(a[0]), "r"(a[1]), "r"(a[2]), "r"(a[3]), "r"(b0), "r"(b1));
}

// ============================================================
// Kernel 0: W_ih fragment image + bias, i/f/o rows prescaled 0.5.
// ============================================================
__global__ void prep(const float* __restrict__ W_ih,
                     const float* __restrict__ b_ih,
                     const float* __restrict__ b_hh) {
    int t = threadIdx.x + blockIdx.x * 256;
    for (int idx = t; idx < GDIM * (IDIM / 2); idx += 256 * 32) {
        int g  = idx >> 6;
        int k2 = (idx & 63) * 2;
        float s = (g < 100 || g >= 150) ? 0.5f : 1.0f;
        float2 wv = *(const float2*)&W_ih[g * IDIM + k2];
        wv.x *= s; wv.y *= s;
        u32 hp, lp;
        split2(wv, hp, lp);
        int nt = g >> 3, nloc = g & 7;
        int kc = k2 >> 4, kloc = k2 & 15;
        int lane = nloc * 4 + ((kloc & 7) >> 1);
        int reg  = kloc >> 3;
        int base = ((kc * 25 + nt) * 32 + lane) * 4;
        g_Bimg[base + reg]     = hp;
        g_Bimg[base + 2 + reg] = lp;
    }
    if (blockIdx.x == 0 && t < GDIM) {
        float s = (t < 100 || t >= 150) ? 0.5f : 1.0f;
        g_bias[t] = (b_ih[t] + b_hh[t]) * s;
    }
}

// ============================================================
// Kernel 0b: prescaled W_hh copy.
// ============================================================
__global__ void prep2(const float* __restrict__ W_hh) {
    int t = threadIdx.x + blockIdx.x * 256;
    if (t < GDIM * HDIM) {
        int g = t / HDIM;
        float s = (g < 100 || g >= 150) ? 0.5f : 1.0f;
        g_Whs[t] = W_hh[t] * s;
    }
}

// ============================================================
// Kernel 1: PERSISTENT HMMA GEMM. Grid 296 (2 blocks/SM), each
// block = one n-half; B slice + bias loaded ONCE, then grid-stride
// over row-tiles with cross-tile A prefetch (at kc==7 the prefetch
// targets the next tile's kc=0; epilogue STGs hide the latency).
// ============================================================
#define SM_BIAS_OFF (13 * 8 * 512)     // max B slice bytes = 53248
#define MMA_SMEM (SM_BIAS_OFF + 800)

__global__ __launch_bounds__(512, 2) void gemm_mma(const float* __restrict__ x) {
    extern __shared__ char sm[];
    u32*   bImg = (u32*)sm;
    float* bias = (float*)(sm + SM_BIAS_OFF);

    const int tid = threadIdx.x;
    const int w   = tid >> 5;
    const int l   = tid & 31;
    const int nh    = blockIdx.x & 1;          // n-half
    const int tile0 = blockIdx.x >> 1;         // 0..147
    const int n0    = nh * 13;
    const int cnt   = nh ? 12 : 13;

    // B slice once
    for (int idx = tid; idx < cnt * 256; idx += 512) {
        int kc  = idx / (cnt * 32);
        int rem = idx - kc * (cnt * 32);
        int src = ((kc * 25 + n0) * 32 + rem) * 4;
        cp16(bImg + idx * 4, g_Bimg + src);
    }
    asm volatile("cp.async.commit_group;\n" ::: "memory");
    if (tid < GDIM) bias[tid] = g_bias[tid];

    const int mt   = w & 7;
    const int nsub = w >> 3;
    const int nst  = nh ? nsub * 6 : nsub * 7;
    const int cw   = nh ? 6 : (nsub ? 6 : 7);

    // per-lane A offset within a tile (m16n8k16 A row-major lane map)
    const int lrow    = mt * 16 + (l >> 2);                    // 0..127
    const int laneoff = lrow * IDIM + (l & 3) * 2;
    const size_t tile_elems = (size_t)PGRID / 2 * 128 * IDIM;  // 148 tiles stride

    const float* xp_cur = x + (size_t)tile0 * 128 * IDIM + laneoff;

    // prefetch first tile kc=0
    float2 v0 = *(const float2*)(xp_cur);
    float2 v1 = *(const float2*)(xp_cur + 8 * IDIM);
    float2 v2 = *(const float2*)(xp_cur + 8);
    float2 v3 = *(const float2*)(xp_cur + 8 * IDIM + 8);

    asm volatile("cp.async.wait_group 0;\n" ::: "memory");
    __syncthreads();

    for (int rt = tile0; rt < NTILES; rt += PGRID / 2) {
        const bool last = (rt + PGRID / 2 >= NTILES);
        const float* xp_nxt = last ? xp_cur : xp_cur + tile_elems;

        float acc[7][4];
#pragma unroll
        for (int n = 0; n < 7; n++)
#pragma unroll
            for (int j = 0; j < 4; j++) acc[n][j] = 0.f;

#pragma unroll
        for (int kc = 0; kc < 8; kc++) {
            u32 ahr[4], alr[4];
            split2f(v0, ahr[0], alr[0]);
            split2f(v1, ahr[1], alr[1]);
            split2f(v2, ahr[2], alr[2]);
            split2f(v3, ahr[3], alr[3]);
            // prefetch: next kc of this tile, or kc=0 of next tile
            const float* pp = (kc < 7) ? (xp_cur + (kc + 1) * 16) : xp_nxt;
            v0 = *(const float2*)(pp);
            v1 = *(const float2*)(pp + 8 * IDIM);
            v2 = *(const float2*)(pp + 8);
            v3 = *(const float2*)(pp + 8 * IDIM + 8);
#pragma unroll
            for (int n = 0; n < 7; n++) {
                if (n < cw) {
                    uint4 b = *(const uint4*)&bImg[((kc * cnt + nst + n) * 32 + l) * 4];
                    mma16816(acc[n], ahr, b.x, b.y);
                    mma16816(acc[n], ahr, b.z, b.w);
                    mma16816(acc[n], alr, b.x, b.y);
                }
            }
        }

        // epilogue: add bias, pack fp16x2, store (hides next-tile LDG)
        {
            int r0 = rt * 128 + lrow;
            int r1 = r0 + 8;
#pragma unroll
            for (int n = 0; n < 7; n++) {
                if (n < cw) {
                    int c = (n0 + nst + n) * 8 + (l & 3) * 2;
                    float2 bv = *(const float2*)&bias[c];
                    float o00 = acc[n][0] + bv.x, o01 = acc[n][1] + bv.y;
                    float o10 = acc[n][2] + bv.x, o11 = acc[n][3] + bv.y;
                    u32 p0, p1;
                    asm("cvt.rn.f16x2.f32 %0, %1, %2;" : "=r"(p0) : "f"(o01), "f"(o00));
                    asm("cvt.rn.f16x2.f32 %0, %1, %2;" : "=r"(p1) : "f"(o11), "f"(o10));
                    *(u32*)&g_xph[(size_t)r0 * GDIM + c] = p0;
                    *(u32*)&g_xph[(size_t)r1 * GDIM + c] = p1;
                }
            }
        }
        xp_cur = xp_nxt;
    }
}

// ============================================================
// Kernel 2: LSTM recurrence + FC head (R15 version, measured 256us).
// 1 batch/block, grid 512, 4 blocks/SM, K-packed f32x2,
// prescaled activations, fp16 x_proj.
// ============================================================
__global__ __launch_bounds__(224, 4) void lstm_rec(
    const float* __restrict__ W_fc, const float* __restrict__ b_fc,
    float* __restrict__ out)
{
    __shared__ alignas(16) float h_sh[52];      // 50 + pad
    __shared__ alignas(16) float gate_sh[GDIM];
    const int b = blockIdx.x;
    const int g = threadIdx.x;

    u64 w2[25];                                 // {w[2j], w[2j+1]} pairs (prescaled)
    if (g < GDIM) {
#pragma unroll
        for (int j = 0; j < 25; j++) {
            float2 wv = *(const float2*)&g_Whs[g * HDIM + 2 * j];
            w2[j] = pk2(wv.x, wv.y);
        }
    }
    if (g < HDIM) h_sh[g] = 0.f;
    float c = 0.f;

    const unsigned short* xp = g_xph + (size_t)b * (TLEN * GDIM);
    unsigned short xc = 0;
    if (g < GDIM) xc = xp[g];
    const bool isg = (g >= 2 * HDIM && g < 3 * HDIM);   // tanh gate
    __syncthreads();

    for (int t = 0; t < TLEN; t++) {
        if (g < GDIM) {
            float xcf;
            asm("cvt.f32.f16 %0, %1;" : "=f"(xcf) : "h"(xc));
            u64 accA = pk2(xcf, 0.f);
            u64 accB = 0ull;
            if (t + 1 < TLEN) xc = xp[(t + 1) * GDIM + g];   // prefetch
#pragma unroll
            for (int j = 0; j < 48; j += 4) {
                ulonglong2 hv = *(const ulonglong2*)&h_sh[j];
                accA = ffma2(hv.x, w2[j >> 1],       accA);
                accB = ffma2(hv.y, w2[(j >> 1) + 1], accB);
            }
            {
                u64 hv = *(const u64*)&h_sh[48];
                accA = ffma2(hv, w2[24], accA);
            }
            float a0, a1;
            up2(fadd2(accA, accB), a0, a1);
            float a = a0 + a1;
            // i/f/o rows prescaled by 0.5: sigmoid = 0.5*tanh(0.5x)+0.5
            gate_sh[g] = isg ? tanha(a) : fmaf(0.5f, tanha(a), 0.5f);
        }
        __syncthreads();
        if (g < HDIM) {
            float iv = gate_sh[g];
            float fv = gate_sh[g + HDIM];
            float gv = gate_sh[g + 2 * HDIM];
            float ov = gate_sh[g + 3 * HDIM];
            c = fmaf(fv, c, iv * gv);
            h_sh[g] = ov * tanha(c);
        }
        __syncthreads();
    }

    // FC head
    if (g < ODIM) {
        float a = b_fc[g];
#pragma unroll
        for (int j = 0; j < HDIM; j++)
            a = fmaf(h_sh[j], W_fc[g * HDIM + j], a);
        out[b * ODIM + g] = a;
    }
}

// ============================================================
// Launch
// ============================================================
extern "C" void kernel_launch(void* const* d_in, const int* in_sizes, int n_in,
                              void* d_out, int out_size) {
    const float* x    = (const float*)d_in[0];
    const float* W_ih = (const float*)d_in[1];
    const float* W_hh = (const float*)d_in[2];
    const float* b_ih = (const float*)d_in[3];
    const float* b_hh = (const float*)d_in[4];
    const float* W_fc = (const float*)d_in[5];
    const float* b_fc = (const float*)d_in[6];
    float* out = (float*)d_out;

    cudaFuncSetAttribute(gemm_mma, cudaFuncAttributeMaxDynamicSharedMemorySize,
                         MMA_SMEM);

    prep<<<32, 256>>>(W_ih, b_ih, b_hh);
    prep2<<<40, 256>>>(W_hh);
    gemm_mma<<<PGRID, 512, MMA_SMEM>>>(x);
    lstm_rec<<<BSZ, 224>>>(W_fc, b_fc, out);
}

// round 17
// speedup vs baseline: 1.0167x; 1.0167x over previous
#include <cuda_runtime.h>
#include <cuda_bf16.h>
#include <cuda_fp16.h>
#include <cstdint>

#define BSZ  512
#define TLEN 512
#define IDIM 128
#define HDIM 50
#define ODIM 10
#define GDIM 200              // 4*H
#define BT   (BSZ * TLEN)     // 262144 rows

typedef unsigned long long u64;
typedef unsigned int u32;

// ---- scratch (device globals; no allocation allowed) ----
__device__ u32   g_Bimg[102400 / 4];        // W_ih bf16 hi/lo frag image (prescaled i/f/o)
__device__ float g_Whs[GDIM * HDIM];        // W_hh prescaled copy
__device__ float g_bias[GDIM];              // (b_ih + b_hh) prescaled
__device__ unsigned short g_xph[(size_t)BT * GDIM];   // x_proj in fp16

// ---- packed f32x2 helpers ----
__device__ __forceinline__ u64 pk2(float lo, float hi) {
    u64 d;
    asm("mov.b64 %0, {%1, %2};" : "=l"(d) : "f"(lo), "f"(hi));
    return d;
}
__device__ __forceinline__ void up2(u64 v, float& lo, float& hi) {
    asm("mov.b64 {%0, %1}, %2;" : "=f"(lo), "=f"(hi) : "l"(v));
}
__device__ __forceinline__ u64 ffma2(u64 a, u64 b, u64 c) {
    u64 d;
    asm("fma.rn.f32x2 %0, %1, %2, %3;" : "=l"(d) : "l"(a), "l"(b), "l"(c));
    return d;
}
__device__ __forceinline__ u64 fadd2(u64 a, u64 b) {
    u64 d;
    asm("add.rn.f32x2 %0, %1, %2;" : "=l"(d) : "l"(a), "l"(b));
    return d;
}
__device__ __forceinline__ float tanha(float x) {
    float r;
    asm("tanh.approx.f32 %0, %1;" : "=f"(r) : "f"(x));
    return r;
}
__device__ __forceinline__ void cp16(void* smem, const void* gmem) {
    unsigned sa = (unsigned)__cvta_generic_to_shared(smem);
    asm volatile("cp.async.cg.shared.global [%0], [%1], 16;\n" :: "r"(sa), "l"(gmem));
}
// slow exact split (prep only)
__device__ __forceinline__ void split_bf16(float v, unsigned short& h, unsigned short& l) {
    __nv_bfloat16 hb = __float2bfloat16_rn(v);
    float lf = v - __bfloat162float(hb);
    __nv_bfloat16 lb = __float2bfloat16_rn(lf);
    h = __bfloat16_as_ushort(hb);
    l = __bfloat16_as_ushort(lb);
}
__device__ __forceinline__ void split2(float2 v, u32& hp, u32& lp) {
    unsigned short h0, l0, h1, l1;
    split_bf16(v.x, h0, l0);
    split_bf16(v.y, h1, l1);
    hp = (u32)h0 | ((u32)h1 << 16);
    lp = (u32)l0 | ((u32)l1 << 16);
}
// fast split: 1 packed cvt for hi, shift/mask reconstruct, 2 subs, 1 packed cvt for lo
__device__ __forceinline__ void split2f(float2 v, u32& hp, u32& lp) {
    asm("cvt.rn.satfinite.bf16x2.f32 %0, %1, %2;" : "=r"(hp) : "f"(v.y), "f"(v.x));
    float h0 = __uint_as_float(hp << 16);
    float h1 = __uint_as_float(hp & 0xffff0000u);
    float l0 = v.x - h0;
    float l1 = v.y - h1;
    asm("cvt.rn.satfinite.bf16x2.f32 %0, %1, %2;" : "=r"(lp) : "f"(l1), "f"(l0));
}
__device__ __forceinline__ void mma16816(float* c, const u32* a, u32 b0, u32 b1) {
    asm volatile(
        "mma.sync.aligned.m16n8k16.row.col.f32.bf16.bf16.f32 "
        "{%0,%1,%2,%3}, {%4,%5,%6,%7}, {%8,%9}, {%0,%1,%2,%3};"
        : "+f"(c[0]), "+f"(c[1]), "+f"(c[2]), "+f"(c[3])
        : "r"(a[0]), "r"(a[1]), "r"(a[2]), "r"(a[3]), "r"(b0), "r"(b1));
}

// ============================================================
// Kernel 0: W_ih fragment image + bias, i/f/o rows prescaled 0.5.
// ============================================================
__global__ void prep(const float* __restrict__ W_ih,
                     const float* __restrict__ b_ih,
                     const float* __restrict__ b_hh) {
    int t = threadIdx.x + blockIdx.x * 256;
    for (int idx = t; idx < GDIM * (IDIM / 2); idx += 256 * 32) {
        int g  = idx >> 6;
        int k2 = (idx & 63) * 2;
        float s = (g < 100 || g >= 150) ? 0.5f : 1.0f;
        float2 wv = *(const float2*)&W_ih[g * IDIM + k2];
        wv.x *= s; wv.y *= s;
        u32 hp, lp;
        split2(wv, hp, lp);
        int nt = g >> 3, nloc = g & 7;
        int kc = k2 >> 4, kloc = k2 & 15;
        int lane = nloc * 4 + ((kloc & 7) >> 1);
        int reg  = kloc >> 3;
        int base = ((kc * 25 + nt) * 32 + lane) * 4;
        g_Bimg[base + reg]     = hp;
        g_Bimg[base + 2 + reg] = lp;
    }
    if (blockIdx.x == 0 && t < GDIM) {
        float s = (t < 100 || t >= 150) ? 0.5f : 1.0f;
        g_bias[t] = (b_ih[t] + b_hh[t]) * s;
    }
}

// ============================================================
// Kernel 0b: prescaled W_hh copy.
// ============================================================
__global__ void prep2(const float* __restrict__ W_hh) {
    int t = threadIdx.x + blockIdx.x * 256;
    if (t < GDIM * HDIM) {
        int g = t / HDIM;
        float s = (g < 100 || g >= 150) ? 0.5f : 1.0f;
        g_Whs[t] = W_hh[t] * s;
    }
}

// ============================================================
// Kernel 1: HMMA GEMM, n-split, 2 blocks/SM; fp16 output.
// (R15 version — measured best)
// ============================================================
#define SM_BIAS_OFF (13 * 8 * 512)     // max B slice bytes = 53248
#define MMA_SMEM (SM_BIAS_OFF + 800)

__global__ __launch_bounds__(512, 2) void gemm_mma(const float* __restrict__ x) {
    extern __shared__ char sm[];
    u32*   bImg = (u32*)sm;
    float* bias = (float*)(sm + SM_BIAS_OFF);

    const int tid = threadIdx.x;
    const int w   = tid >> 5;
    const int l   = tid & 31;
    const int row0 = (blockIdx.x >> 1) * 128;
    const int nh   = blockIdx.x & 1;
    const int n0   = nh * 13;
    const int cnt  = nh ? 12 : 13;

    for (int idx = tid; idx < cnt * 256; idx += 512) {
        int kc  = idx / (cnt * 32);
        int rem = idx - kc * (cnt * 32);
        int src = ((kc * 25 + n0) * 32 + rem) * 4;
        cp16(bImg + idx * 4, g_Bimg + src);
    }
    asm volatile("cp.async.commit_group;\n" ::: "memory");
    if (tid < GDIM) bias[tid] = g_bias[tid];

    const int mt   = w & 7;
    const int nsub = w >> 3;
    const int nst  = nh ? nsub * 6 : nsub * 7;
    const int cw   = nh ? 6 : (nsub ? 6 : 7);

    const int rA = row0 + mt * 16 + (l >> 2);
    const float* xr0 = x + (size_t)rA * IDIM + (l & 3) * 2;
    const float* xr1 = xr0 + 8 * IDIM;

    float acc[7][4];
#pragma unroll
    for (int n = 0; n < 7; n++)
#pragma unroll
        for (int j = 0; j < 4; j++) acc[n][j] = 0.f;

    float2 v0 = *(const float2*)(xr0);
    float2 v1 = *(const float2*)(xr1);
    float2 v2 = *(const float2*)(xr0 + 8);
    float2 v3 = *(const float2*)(xr1 + 8);

    asm volatile("cp.async.wait_group 0;\n" ::: "memory");
    __syncthreads();

#pragma unroll
    for (int kc = 0; kc < 8; kc++) {
        u32 ahr[4], alr[4];
        split2f(v0, ahr[0], alr[0]);
        split2f(v1, ahr[1], alr[1]);
        split2f(v2, ahr[2], alr[2]);
        split2f(v3, ahr[3], alr[3]);
        if (kc + 1 < 8) {
            int ko = (kc + 1) * 16;
            v0 = *(const float2*)(xr0 + ko);
            v1 = *(const float2*)(xr1 + ko);
            v2 = *(const float2*)(xr0 + ko + 8);
            v3 = *(const float2*)(xr1 + ko + 8);
        }
#pragma unroll
        for (int n = 0; n < 7; n++) {
            if (n < cw) {
                uint4 b = *(const uint4*)&bImg[((kc * cnt + nst + n) * 32 + l) * 4];
                mma16816(acc[n], ahr, b.x, b.y);
                mma16816(acc[n], ahr, b.z, b.w);
                mma16816(acc[n], alr, b.x, b.y);
            }
        }
    }

    {
        int r0 = row0 + mt * 16 + (l >> 2);
        int r1 = r0 + 8;
#pragma unroll
        for (int n = 0; n < 7; n++) {
            if (n < cw) {
                int c = (n0 + nst + n) * 8 + (l & 3) * 2;
                float2 bv = *(const float2*)&bias[c];
                float o00 = acc[n][0] + bv.x, o01 = acc[n][1] + bv.y;
                float o10 = acc[n][2] + bv.x, o11 = acc[n][3] + bv.y;
                u32 p0, p1;
                asm("cvt.rn.f16x2.f32 %0, %1, %2;" : "=r"(p0) : "f"(o01), "f"(o00));
                asm("cvt.rn.f16x2.f32 %0, %1, %2;" : "=r"(p1) : "f"(o11), "f"(o10));
                *(u32*)&g_xph[(size_t)r0 * GDIM + c] = p0;
                *(u32*)&g_xph[(size_t)r1 * GDIM + c] = p1;
            }
        }
    }
}

// ============================================================
// Kernel 2: LSTM recurrence + FC head. 1 batch/block, grid 512,
// 128 threads (4 warps), 4 blocks/SM. Each thread owns TWO gate
// rows (type t, units 2p and 2p+1): one h-broadcast LDS feeds
// both rows -> LDS wavefronts halved vs 1-gate/thread. Weights =
// 100 regs (two K-packed rows). Same arithmetic order per gate
// as R15 (identical numerics).
// ============================================================
__global__ __launch_bounds__(128, 4) void lstm_rec(
    const float* __restrict__ W_fc, const float* __restrict__ b_fc,
    float* __restrict__ out)
{
    __shared__ alignas(16) float h_sh[52];      // 50 + pad
    __shared__ alignas(16) float gate_sh[GDIM];
    const int b = blockIdx.x;
    const int tid = threadIdx.x;
    const bool act = (tid < 100);
    const int ty = tid / 25;            // gate type 0..3 (i,f,g,o)
    const int p  = tid % 25;            // unit pair
    const int r0 = ty * HDIM + 2 * p;   // first gate row (even)

    u64 w2a[25], w2b[25];               // K-packed pairs for rows r0, r0+1
    if (act) {
#pragma unroll
        for (int j = 0; j < 25; j++) {
            float2 wa = *(const float2*)&g_Whs[r0 * HDIM + 2 * j];
            float2 wb = *(const float2*)&g_Whs[(r0 + 1) * HDIM + 2 * j];
            w2a[j] = pk2(wa.x, wa.y);
            w2b[j] = pk2(wb.x, wb.y);
        }
    }
    if (tid < 52) h_sh[tid] = 0.f;
    float c0 = 0.f, c1 = 0.f;           // cell state (threads tid<50: units 2*tid, 2*tid+1? no -> see update)

    // x_proj: rows r0, r0+1 are adjacent -> one fp16x2 (u32) load
    const u32* xq = (const u32*)(g_xph + (size_t)b * (TLEN * GDIM));
    u32 xw = 0;
    if (act) xw = xq[r0 >> 1];          // t=0
    const bool isg = (ty == 2);
    __syncthreads();

    for (int t = 0; t < TLEN; t++) {
        if (act) {
            float2 xf = __half22float2(*(__half2*)&xw);
            u64 a0A = pk2(xf.x, 0.f), a0B = 0ull;
            u64 a1A = pk2(xf.y, 0.f), a1B = 0ull;
            if (t + 1 < TLEN) xw = xq[(t + 1) * (GDIM / 2) + (r0 >> 1)];
#pragma unroll
            for (int j = 0; j < 48; j += 4) {
                ulonglong2 hv = *(const ulonglong2*)&h_sh[j];
                a0A = ffma2(hv.x, w2a[j >> 1],       a0A);
                a0B = ffma2(hv.y, w2a[(j >> 1) + 1], a0B);
                a1A = ffma2(hv.x, w2b[j >> 1],       a1A);
                a1B = ffma2(hv.y, w2b[(j >> 1) + 1], a1B);
            }
            {
                u64 hv = *(const u64*)&h_sh[48];
                a0A = ffma2(hv, w2a[24], a0A);
                a1A = ffma2(hv, w2b[24], a1A);
            }
            float s00, s01, s10, s11;
            up2(fadd2(a0A, a0B), s00, s01);
            up2(fadd2(a1A, a1B), s10, s11);
            float g0 = s00 + s01;
            float g1 = s10 + s11;
            float2 res;
            if (isg) {
                res = make_float2(tanha(g0), tanha(g1));
            } else {
                res = make_float2(fmaf(0.5f, tanha(g0), 0.5f),
                                  fmaf(0.5f, tanha(g1), 0.5f));
            }
            *(float2*)&gate_sh[r0] = res;   // r0 even -> 8B aligned
        }
        __syncthreads();
        if (tid < 25) {                     // unit pair 2*tid, 2*tid+1
            int u0 = 2 * tid;
            float2 iv = *(const float2*)&gate_sh[u0];
            float2 fv = *(const float2*)&gate_sh[u0 + HDIM];
            float2 gv = *(const float2*)&gate_sh[u0 + 2 * HDIM];
            float2 ov = *(const float2*)&gate_sh[u0 + 3 * HDIM];
            c0 = fmaf(fv.x, c0, iv.x * gv.x);
            c1 = fmaf(fv.y, c1, iv.y * gv.y);
            *(float2*)&h_sh[u0] = make_float2(ov.x * tanha(c0), ov.y * tanha(c1));
        }
        __syncthreads();
    }

    // FC head
    if (tid < ODIM) {
        float a = b_fc[tid];
#pragma unroll
        for (int j = 0; j < HDIM; j++)
            a = fmaf(h_sh[j], W_fc[tid * HDIM + j], a);
        out[b * ODIM + tid] = a;
    }
}

// ============================================================
// Launch
// ============================================================
extern "C" void kernel_launch(void* const* d_in, const int* in_sizes, int n_in,
                              void* d_out, int out_size) {
    const float* x    = (const float*)d_in[0];
    const float* W_ih = (const float*)d_in[1];
    const float* W_hh = (const float*)d_in[2];
    const float* b_ih = (const float*)d_in[3];
    const float* b_hh = (const float*)d_in[4];
    const float* W_fc = (const float*)d_in[5];
    const float* b_fc = (const float*)d_in[6];
    float* out = (float*)d_out;

    cudaFuncSetAttribute(gemm_mma, cudaFuncAttributeMaxDynamicSharedMemorySize,
                         MMA_SMEM);

    prep<<<32, 256>>>(W_ih, b_ih, b_hh);
    prep2<<<40, 256>>>(W_hh);
    gemm_mma<<<(BT / 128) * 2, 512, MMA_SMEM>>>(x);
    lstm_rec<<<BSZ, 128>>>(W_fc, b_fc, out);
}